// round 17
// baseline (speedup 1.0000x reference)
#include <cuda_runtime.h>
#include <cstdint>

#define MAX_E 100000
#define MAX_T 1000000
#define CCH   64
#define SCAN_BLK 512
#define MAX_SCAN_BLOCKS ((MAX_E + SCAN_BLK - 1) / SCAN_BLK)
#define TPB1 128   // pass1: triplets per block

// Scratch (device globals — zero at module load; g_cnt/g_cursor are
// re-zeroed by k_edge at the end of every run => zero on entry always).
__device__ float4   g_rnorm4[MAX_E];
__device__ unsigned g_cnt[MAX_E];
__device__ unsigned g_off[MAX_E];    // block-local exclusive prefix (scan1)
__device__ unsigned g_cursor[MAX_E];
__device__ unsigned g_bsum[MAX_SCAN_BLOCKS];  // exclusive block offsets (scan2)
__device__ int2     g_sd[MAX_T];     // {src, dst}, CSR(dst)-ordered
__device__ int2     g_se[MAX_T];     // {src, exp(logit) bits}, CSR-ordered

// ---------------------------------------------------------------------------
// prep+count fused: unit bond dirs for i<E; degree histogram for i<T
// ---------------------------------------------------------------------------
__global__ void k_prep_count(const float* __restrict__ r,
                             const int* __restrict__ tdst, int E, int T) {
    int i = blockIdx.x * blockDim.x + threadIdx.x;
    if (i < E) {
        float x = r[3 * i + 0], y = r[3 * i + 1], z = r[3 * i + 2];
        float inv = rsqrtf(x * x + y * y + z * z);
        g_rnorm4[i] = make_float4(x * inv, y * inv, z * inv, 0.0f);
    }
    if (i < T) atomicAdd(&g_cnt[tdst[i]], 1u);
}

// -------- 2-kernel scan; final block-offset add folded into consumers -------
__global__ void k_scan1(int E) {
    __shared__ unsigned sh[SCAN_BLK];
    int i = blockIdx.x * SCAN_BLK + threadIdx.x;
    unsigned v = (i < E) ? g_cnt[i] : 0u;
    sh[threadIdx.x] = v;
    __syncthreads();
    unsigned incl = v;
    for (int ofs = 1; ofs < SCAN_BLK; ofs <<= 1) {
        unsigned add = (threadIdx.x >= ofs) ? sh[threadIdx.x - ofs] : 0u;
        __syncthreads();
        incl += add;
        sh[threadIdx.x] = incl;
        __syncthreads();
    }
    if (i < E) g_off[i] = incl - v;          // block-local exclusive
    if (threadIdx.x == SCAN_BLK - 1) g_bsum[blockIdx.x] = incl;
}

__global__ void k_scan2(int nb) {
    __shared__ unsigned sh[SCAN_BLK];
    unsigned v = (threadIdx.x < nb) ? g_bsum[threadIdx.x] : 0u;
    sh[threadIdx.x] = v;
    __syncthreads();
    unsigned incl = v;
    for (int ofs = 1; ofs < SCAN_BLK; ofs <<= 1) {
        unsigned add = (threadIdx.x >= ofs) ? sh[threadIdx.x - ofs] : 0u;
        __syncthreads();
        incl += add;
        sh[threadIdx.x] = incl;
        __syncthreads();
    }
    if (threadIdx.x < nb) g_bsum[threadIdx.x] = incl - v;   // exclusive blocks
}

__device__ __forceinline__ unsigned edge_base(int e) {
    return g_off[e] + g_bsum[e >> 9];        // SCAN_BLK == 512
}

// ---------------------------------------------------------------------------
// perm: scatter triplets into CSR(dst) order — ONE int2 {src,dst} STG.64
// per triplet (one cache line touched instead of two separate arrays)
// ---------------------------------------------------------------------------
__global__ void k_perm(const int* __restrict__ tsrc, const int* __restrict__ tdst, int T) {
    int t = blockIdx.x * blockDim.x + threadIdx.x;
    if (t >= T) return;
    int d = tdst[t];
    unsigned pos = edge_base(d) + atomicAdd(&g_cursor[d], 1u);
    g_sd[pos] = make_int2(tsrc[t], d);
}

// ---------------------------------------------------------------------------
// pass1 (compute loop R5-verbatim): exp(logit) in CSR order.
//  - xij[src] staged to smem (coalesced, odd stride 65)
//  - xij[dst] direct: CSR adjacency -> few distinct rows/warp, L1-hits
//  - Chebyshev 3-term recurrence (1 FMA/channel)
//  - per-channel INDEPENDENT silu intrinsics (restructured variants repeatedly
//    measured slower — do not lengthen dependency chains)
//  - emits {src, exp(a)} packed so k_edge streams one array
//  No softmax max subtraction (|a| << 88; alpha identical — validated R4-R16)
// ---------------------------------------------------------------------------
__global__ void __launch_bounds__(TPB1)
k_pass1(const float* __restrict__ xij, const float* __restrict__ attn, int T) {
    __shared__ float sx[TPB1 * 65];
    __shared__ float sat[CCH];
    int tid = threadIdx.x;
    int base = blockIdx.x * TPB1;
    if (tid < CCH) sat[tid] = attn[tid];

    int lane = tid & 31, w = tid >> 5;
    for (int j = w; j < TPB1; j += TPB1 / 32) {
        int t = base + j;
        if (t < T) {
            int s = g_sd[t].x;             // warp-uniform -> broadcast
            float2 v = __ldg((const float2*)(xij + (size_t)s * CCH) + lane);
            sx[j * 65 + 2 * lane]     = v.x;
            sx[j * 65 + 2 * lane + 1] = v.y;
        }
    }
    __syncthreads();

    int t = base + tid;
    if (t >= T) return;
    int2 p = g_sd[t];
    int s = p.x, d = p.y;

    float4 rs = __ldg(&g_rnorm4[s]);
    float4 rd = __ldg(&g_rnorm4[d]);
    float cth = rs.x * rd.x + rs.y * rd.y + rs.z * rd.z;
    cth = fminf(fmaxf(cth, -1.0f + 1e-6f), 1.0f - 1e-6f);
    float c2 = 2.0f * cth;
    float zp = cth, zc = 1.0f;   // T_{-1}, T_0

    const float4* xd = (const float4*)(xij + (size_t)d * CCH);
    const float* row = &sx[tid * 65];
    float a = 0.0f;

#pragma unroll
    for (int k = 0; k < CCH / 4; k++) {
        float4 D = __ldg(xd + k);
        float dv[4] = {D.x, D.y, D.z, D.w};
#pragma unroll
        for (int j = 0; j < 4; j++) {
            int c = 4 * k + j;
            float v = zc + row[c] + dv[j];
            float e = __fdividef(v, 1.0f + __expf(-v));   // silu
            a = fmaf(e, sat[c], a);
            float zn = fmaf(c2, zc, -zp);                 // Chebyshev step
            zp = zc; zc = zn;
        }
    }
    g_se[t] = make_int2(s, __float_as_int(__expf(a)));   // coalesced STG.64
}

// ---------------------------------------------------------------------------
// edge: warp-per-edge aggregate: ft = (sum ex*x[src]) / sum ex.
// Streams ONE packed array (g_se). Lane owns channels {2*lane, 2*lane+1}.
// Resets g_cnt / g_cursor for the next run (self-restoring global state).
// ---------------------------------------------------------------------------
__global__ void __launch_bounds__(256)
k_edge(const float* __restrict__ xij, float* __restrict__ ft, int E) {
    int warp = (blockIdx.x * blockDim.x + threadIdx.x) >> 5;
    int lane = threadIdx.x & 31;
    if (warp >= E) return;

    int base = (int)edge_base(warp);
    int deg  = (int)g_cnt[warp];

    float ax = 0.0f, ay = 0.0f, den = 0.0f;

    int i = 0;
    for (; i + 4 <= deg; i += 4) {
        int2 p0 = __ldg(&g_se[base + i + 0]);
        int2 p1 = __ldg(&g_se[base + i + 1]);
        int2 p2 = __ldg(&g_se[base + i + 2]);
        int2 p3 = __ldg(&g_se[base + i + 3]);
        float2 v0 = __ldg((const float2*)(xij + (size_t)p0.x * CCH) + lane);
        float2 v1 = __ldg((const float2*)(xij + (size_t)p1.x * CCH) + lane);
        float2 v2 = __ldg((const float2*)(xij + (size_t)p2.x * CCH) + lane);
        float2 v3 = __ldg((const float2*)(xij + (size_t)p3.x * CCH) + lane);
        float e0 = __int_as_float(p0.y), e1 = __int_as_float(p1.y);
        float e2 = __int_as_float(p2.y), e3 = __int_as_float(p3.y);
        den += (e0 + e1) + (e2 + e3);
        ax = fmaf(e0, v0.x, ax); ay = fmaf(e0, v0.y, ay);
        ax = fmaf(e1, v1.x, ax); ay = fmaf(e1, v1.y, ay);
        ax = fmaf(e2, v2.x, ax); ay = fmaf(e2, v2.y, ay);
        ax = fmaf(e3, v3.x, ax); ay = fmaf(e3, v3.y, ay);
    }
    for (; i < deg; i++) {
        int2 p0 = __ldg(&g_se[base + i]);
        float2 v0 = __ldg((const float2*)(xij + (size_t)p0.x * CCH) + lane);
        float e0 = __int_as_float(p0.y);
        den += e0;
        ax = fmaf(e0, v0.x, ax); ay = fmaf(e0, v0.y, ay);
    }

    float inv = (deg > 0) ? __fdividef(1.0f, den) : 0.0f;
    *((float2*)(ft + (size_t)warp * CCH) + lane) = make_float2(ax * inv, ay * inv);

    if (lane == 0) {                // restore invariant for next run
        g_cnt[warp] = 0u;
        g_cursor[warp] = 0u;
    }
}

// ---------------------------------------------------------------------------
extern "C" void kernel_launch(void* const* d_in, const int* in_sizes, int n_in,
                              void* d_out, int out_size) {
    const float* xij  = (const float*)d_in[0];
    const float* r    = (const float*)d_in[1];
    const float* attn = (const float*)d_in[2];
    const int*   tsrc = (const int*)d_in[3];
    const int*   tdst = (const int*)d_in[4];
    float* ft = (float*)d_out;

    int E = in_sizes[1] / 3;
    int T = in_sizes[3];
    int nsb = (E + SCAN_BLK - 1) / SCAN_BLK;
    int nmx = (T > E) ? T : E;

    k_prep_count<<<(nmx + 255) / 256, 256>>>(r, tdst, E, T);
    k_scan1<<<nsb, SCAN_BLK>>>(E);
    k_scan2<<<1,   SCAN_BLK>>>(nsb);
    k_perm <<<(T + 255) / 256, 256>>>(tsrc, tdst, T);
    k_pass1<<<(T + TPB1 - 1) / TPB1, TPB1>>>(xij, attn, T);
    k_edge <<<(E * 32 + 255) / 256, 256>>>(xij, ft, E);
}